// round 2
// baseline (speedup 1.0000x reference)
#include <cuda_runtime.h>

// UpsampleInterp: [1, 80, 96, 112, 16] f32 -> [1, 160, 192, 224, 16] f32
// 2x multilinear upsampling per spatial axis with edge clamp.
//
// R2: parity-split scatter. One thread per (input voxel, x-parity, channel
// quad). Thread (z,y,x,p,c4) writes the 4 outputs at output-x = 2x+p
// (the 2x2 z/y fan-out). Lane layout lane = 8*x_lo + 4*p + c4 makes every
// warp store instruction a fully dense contiguous 512 B range (vs 50%
// density in R1). Loads: 8 corners/thread; p=0 threads' x1 loads duplicate
// x0 addresses (coalesced broadcast, no extra DRAM sectors).

#define DD 80
#define HH 96
#define WW 112
// C = 16 floats = 4 float4 quads per voxel

__device__ __forceinline__ float4 f4_avg2(float4 a, float4 b) {
    return make_float4(0.5f * (a.x + b.x), 0.5f * (a.y + b.y),
                       0.5f * (a.z + b.z), 0.5f * (a.w + b.w));
}
__device__ __forceinline__ float4 f4_avg4(float4 a, float4 b, float4 c, float4 d) {
    return make_float4(0.25f * (a.x + b.x + c.x + d.x),
                       0.25f * (a.y + b.y + c.y + d.y),
                       0.25f * (a.z + b.z + c.z + d.z),
                       0.25f * (a.w + b.w + c.w + d.w));
}

__global__ void __launch_bounds__(256)
upsample_2x_kernel(const float4* __restrict__ in, float4* __restrict__ out) {
    int tid = blockIdx.x * 256 + threadIdx.x;
    // total threads = DD*HH*WW*2*4 = 6,881,280 (grid sized exactly)

    int c4 = tid & 3;
    int p  = (tid >> 2) & 1;
    int t  = tid >> 3;
    int x  = t % WW;
    int t2 = t / WW;
    int y  = t2 % HH;
    int z  = t2 / HH;

    int yp = min(y + 1, HH - 1);
    int zp = min(z + 1, DD - 1);
    int x1 = p ? min(x + 1, WW - 1) : x;

    // input float4 index
    #define IIDX(zz, yy, xx) ((((zz) * HH + (yy)) * WW + (xx)) * 4 + c4)
    // corners at x (A) and x1 (B). For p=0, B duplicates A (exact avg2(a,a)=a).
    float4 a00 = in[IIDX(z,  y,  x )];
    float4 b00 = in[IIDX(z,  y,  x1)];
    float4 a01 = in[IIDX(z,  yp, x )];
    float4 b01 = in[IIDX(z,  yp, x1)];
    float4 a10 = in[IIDX(zp, y,  x )];
    float4 b10 = in[IIDX(zp, y,  x1)];
    float4 a11 = in[IIDX(zp, yp, x )];
    float4 b11 = in[IIDX(zp, yp, x1)];
    #undef IIDX

    // x-blend: u_{zy} = value at output-x = 2x+p for input plane (z+dz, y+dy)
    float4 u00 = f4_avg2(a00, b00);
    float4 u01 = f4_avg2(a01, b01);
    float4 u10 = f4_avg2(a10, b10);
    float4 u11 = f4_avg2(a11, b11);

    int zo = 2 * z, yo = 2 * y, xop = 2 * x + p;
    // output float4 index (dims 2*DD x 2*HH x 2*WW)
    #define OIDX(zz, yy) ((((zz) * (2 * HH) + (yy)) * (2 * WW) + xop) * 4 + c4)

    __stcs(&out[OIDX(zo,     yo    )], u00);
    __stcs(&out[OIDX(zo,     yo + 1)], f4_avg2(u00, u01));
    __stcs(&out[OIDX(zo + 1, yo    )], f4_avg2(u00, u10));
    __stcs(&out[OIDX(zo + 1, yo + 1)], f4_avg4(u00, u01, u10, u11));
    #undef OIDX
}

extern "C" void kernel_launch(void* const* d_in, const int* in_sizes, int n_in,
                              void* d_out, int out_size) {
    const float4* in  = (const float4*)d_in[0];
    float4*       out = (float4*)d_out;

    const int total_threads = DD * HH * WW * 2 * 4;  // 6,881,280
    const int block = 256;
    const int grid  = total_threads / block;         // 26,880 exactly

    upsample_2x_kernel<<<grid, block>>>(in, out);
}